// round 1
// baseline (speedup 1.0000x reference)
#include <cuda_runtime.h>
#include <math.h>

#define LQ 64
#define BQ 256
#define TQ 32
#define EQ 256
#define HQ 256
#define GQ 768      // 3*H
#define KQ 32
#define NRQ 8192    // B*K beam rows
#define NTOTQ 8448  // beam rows + B path rows

typedef unsigned long long u64;

// ---------------- device scratch (no allocations allowed) ----------------
__device__ float d_XG[33 * GQ];      // precomputed x-gates per tag (includes b_ih)
__device__ float d_Wt[HQ * GQ];      // W_hh transposed: Wt[k*G + c] = W_hh[c*H + k]
__device__ float d_WtL[HQ * TQ];     // W_lin transposed: WtL[k*T + t] = W_lin[t*H + k]
__device__ float d_h1[HQ];
__device__ float d_trans0[TQ];
__device__ float d_Hid[NTOTQ * HQ];
__device__ float d_Hnew[NTOTQ * HQ];
__device__ float d_Sc[BQ * KQ];
__device__ int   d_Btags[BQ * KQ];
__device__ float d_Cand[NTOTQ * TQ];
__device__ float d_PS[BQ];

// ---------------- helpers ----------------
__device__ __forceinline__ float fsig(float x)  { return 1.0f / (1.0f + __expf(-x)); }
__device__ __forceinline__ float ftanh(float x) { return 2.0f / (1.0f + __expf(-2.0f * x)) - 1.0f; }

__device__ __forceinline__ u64 pack2(float lo, float hi) {
    u64 r;
    asm("mov.b64 %0, {%1, %2};" : "=l"(r) : "f"(lo), "f"(hi));
    return r;
}
// packed fp32x2 FMA (Blackwell): d = a*b + d, lane-wise
__device__ __forceinline__ void fma2(u64 &d, u64 a, u64 b) {
    asm("fma.rn.f32x2 %0, %1, %2, %0;" : "+l"(d) : "l"(a), "l"(b));
}

// ---------------- prep: XG[33][768] = W_ih @ emb[t] + b_ih ----------------
__global__ void k_prep_xg(const float* __restrict__ W_ih,
                          const float* __restrict__ emb,
                          const float* __restrict__ b_ih) {
    int o = (blockIdx.x * blockDim.x + threadIdx.x) >> 5;
    int lane = threadIdx.x & 31;
    if (o >= 33 * GQ) return;
    int t = o / GQ, c = o % GQ;
    const float* wr = W_ih + c * EQ;
    const float* er = emb + t * EQ;
    float acc = 0.f;
    for (int k = lane; k < EQ; k += 32) acc += wr[k] * er[k];
    #pragma unroll
    for (int off = 16; off; off >>= 1) acc += __shfl_down_sync(0xffffffffu, acc, off);
    if (lane == 0) d_XG[o] = acc + b_ih[c];
}

// ---------------- prep: transposes ----------------
__global__ void k_prep_tr(const float* __restrict__ W_hh,
                          const float* __restrict__ W_lin) {
    int idx = blockIdx.x * blockDim.x + threadIdx.x;
    if (idx < GQ * HQ) {
        int c = idx / HQ, k = idx % HQ;
        d_Wt[k * GQ + c] = W_hh[idx];
    } else {
        int i2 = idx - GQ * HQ;
        if (i2 < TQ * HQ) {
            int t = i2 / HQ, k = i2 % HQ;
            d_WtL[k * TQ + t] = W_lin[i2];
        }
    }
}

// ---------------- prep: h1 = gru(emb[T], 0) and trans0 = lin(h1) ----------------
__global__ void k_prep_h1(const float* __restrict__ b_hh,
                          const float* __restrict__ W_lin,
                          const float* __restrict__ b_lin) {
    __shared__ float h1s[HQ];
    int j = threadIdx.x;
    float ir  = d_XG[32 * GQ + j];
    float iz  = d_XG[32 * GQ + HQ + j];
    float in_ = d_XG[32 * GQ + 2 * HQ + j];
    float r = fsig(ir + b_hh[j]);
    float z = fsig(iz + b_hh[HQ + j]);
    float n = ftanh(in_ + r * b_hh[2 * HQ + j]);
    float h = (1.f - z) * n;   // h0 == 0
    h1s[j] = h;
    d_h1[j] = h;
    __syncthreads();
    if (j < TQ) {
        float acc = b_lin[j];
        const float* wr = W_lin + j * HQ;
        for (int k = 0; k < HQ; k++) acc += wr[k] * h1s[k];
        d_trans0[j] = acc;
    }
}

// ---------------- prep: initial scores / beams / hidden / path score ----------------
__global__ void k_prep_init(const float* __restrict__ emis,
                            const int* __restrict__ tags,
                            const float* __restrict__ mask) {
    int w = threadIdx.x >> 5, lane = threadIdx.x & 31;
    int b = blockIdx.x * 8 + w;
    float m0 = mask[b];
    float v = (d_trans0[lane] + emis[b * TQ + lane]) * m0;
    // rank = full descending sort with tie -> smaller index (exact jax top_k for K==T)
    int rank = 0;
    for (int j = 0; j < 32; j++) {
        float vj = __shfl_sync(0xffffffffu, v, j);
        rank += (vj > v) || (vj == v && j < lane);
    }
    d_Sc[b * KQ + rank]    = v;
    d_Btags[b * KQ + rank] = lane;
    if (lane == 0) {
        int t0 = tags[b];
        d_PS[b] = (d_trans0[t0] + emis[b * TQ + t0]) * m0;
    }
    // broadcast h1 to all 32 beams + path row
    for (int r = 0; r < KQ; r++) {
        float* dst = d_Hid + (b * KQ + r) * HQ;
        for (int c = lane; c < HQ; c += 32) dst[c] = d_h1[c];
    }
    float* dst = d_Hid + (NRQ + b) * HQ;
    for (int c = lane; c < HQ; c += 32) dst[c] = d_h1[c];
}

// ---------------- main GRU step: 32 rows/block, FFMA2-packed GEMM + gates + lin ----------------
__global__ void __launch_bounds__(256, 1)
k_gru_step(int step,
           const float* __restrict__ emis,
           const int* __restrict__ tags,
           const float* __restrict__ mask,
           const float* __restrict__ b_hh,
           const float* __restrict__ b_lin) {
    __shared__ float2 Hs2[16][HQ];   // 32KB: row-pairs of H tile; reused as HN[32][256] later
    __shared__ int stag[32];
    int tid = threadIdx.x;
    int row0 = blockIdx.x * 32;

    if (tid < 32) {
        int row = row0 + tid;
        stag[tid] = (row < NRQ) ? d_Btags[row] : tags[(step - 1) * BQ + (row - NRQ)];
    }
    {
        const float* src = d_Hid + row0 * HQ;
        #pragma unroll
        for (int i = 0; i < 32; i++) {
            float v = src[i * HQ + tid];
            ((float*)&Hs2[i >> 1][tid])[i & 1] = v;
        }
    }
    __syncthreads();

    // GEMM: gates[row][c] = sum_k H[row][k] * W_hh[c][k], c in {tid, tid+256, tid+512}
    u64 acc0[16], acc1[16], acc2[16];
    #pragma unroll
    for (int p = 0; p < 16; p++) { acc0[p] = 0ull; acc1[p] = 0ull; acc2[p] = 0ull; }

    const float* W0p = d_Wt + tid;
    #pragma unroll 2
    for (int k = 0; k < HQ; k++) {
        float w0 = W0p[k * GQ];
        float w1 = W0p[k * GQ + 256];
        float w2 = W0p[k * GQ + 512];
        u64 W0 = pack2(w0, w0), W1 = pack2(w1, w1), W2 = pack2(w2, w2);
        #pragma unroll
        for (int p = 0; p < 16; p++) {
            u64 h = *reinterpret_cast<const u64*>(&Hs2[p][k]);
            fma2(acc0[p], h, W0);
            fma2(acc1[p], h, W1);
            fma2(acc2[p], h, W2);
        }
    }

    // gates + new hidden
    float bh0 = b_hh[tid], bh1 = b_hh[256 + tid], bh2 = b_hh[512 + tid];
    float hn_arr[32];
    #pragma unroll
    for (int p = 0; p < 16; p++) {
        float2 a0 = *(float2*)&acc0[p];
        float2 a1 = *(float2*)&acc1[p];
        float2 a2 = *(float2*)&acc2[p];
        float2 hold = Hs2[p][tid];
        #pragma unroll
        for (int s = 0; s < 2; s++) {
            int r = 2 * p + s;
            float g0 = s ? a0.y : a0.x;
            float g1 = s ? a1.y : a1.x;
            float g2 = s ? a2.y : a2.x;
            int tg = stag[r];
            const float* gi = d_XG + tg * GQ;
            float rr = fsig(gi[tid] + g0 + bh0);
            float zz = fsig(gi[256 + tid] + g1 + bh1);
            float nn = ftanh(gi[512 + tid] + rr * (g2 + bh2));
            float ho = s ? hold.y : hold.x;
            float hv = nn + zz * (ho - nn);   // (1-z)*n + z*h
            hn_arr[r] = hv;
            d_Hnew[(row0 + r) * HQ + tid] = hv;
        }
    }
    __syncthreads();
    float* HN = (float*)Hs2;   // reuse smem
    #pragma unroll
    for (int r = 0; r < 32; r++) HN[r * HQ + tid] = hn_arr[r];
    __syncthreads();

    // TR = HN @ W_lin^T + b_lin; warp w handles rows 4w..4w+3, lane = tag column
    int w = tid >> 5, lane = tid & 31;
    float t_acc[4];
    #pragma unroll
    for (int q = 0; q < 4; q++) t_acc[q] = b_lin[lane];
    const float* hrow = HN + (4 * w) * HQ;
    for (int k = 0; k < HQ; k++) {
        float wl = d_WtL[k * TQ + lane];
        #pragma unroll
        for (int q = 0; q < 4; q++) t_acc[q] += hrow[q * HQ + k] * wl;
    }

    // epilogue: candidates for beam rows, raw TR for path rows
    #pragma unroll
    for (int q = 0; q < 4; q++) {
        int r = 4 * w + q;
        int row = row0 + r;
        float val;
        if (row < NRQ) {
            int b = row >> 5;
            float base = d_Sc[(row & ~31) + stag[r]];   // quirk: gather scores by beam TAG id
            float em = emis[(step * BQ + b) * TQ + lane];
            float m = mask[step * BQ + b];
            val = base + (t_acc[q] + em) * m;
        } else {
            val = t_acc[q];
        }
        d_Cand[row * TQ + lane] = val;
    }
}

// ---------------- top-32 select + beam gather + path-score update ----------------
__global__ void k_select(int step,
                         const float* __restrict__ emis,
                         const int* __restrict__ tags,
                         const float* __restrict__ mask) {
    __shared__ float sv[8][KQ * TQ];
    __shared__ int spar[8][KQ];
    int w = threadIdx.x >> 5, lane = threadIdx.x & 31;
    int b = blockIdx.x * 8 + w;
    float* svw = sv[w];
    const float* cb = d_Cand + b * (KQ * TQ);
    #pragma unroll
    for (int j = 0; j < 32; j++) svw[j * 32 + lane] = cb[j * 32 + lane];
    __syncwarp();

    for (int i = 0; i < KQ; i++) {
        float bv = -INFINITY; int bi = 0x7fffffff;
        #pragma unroll
        for (int j = 0; j < 32; j++) {
            float vv = svw[j * 32 + lane];
            if (vv > bv) { bv = vv; bi = j * 32 + lane; }   // '>' keeps smallest idx on ties
        }
        #pragma unroll
        for (int off = 16; off; off >>= 1) {
            float ov = __shfl_down_sync(0xffffffffu, bv, off);
            int   oi = __shfl_down_sync(0xffffffffu, bi, off);
            if (ov > bv || (ov == bv && oi < bi)) { bv = ov; bi = oi; }
        }
        bv = __shfl_sync(0xffffffffu, bv, 0);
        bi = __shfl_sync(0xffffffffu, bi, 0);
        if (lane == 0) {
            d_Sc[b * KQ + i]    = bv;
            d_Btags[b * KQ + i] = bi & 31;
            spar[w][i]          = bi >> 5;
            svw[bi] = -INFINITY;
        }
        __syncwarp();
    }

    // gather new hidden by parent
    for (int i = 0; i < KQ; i++) {
        int p = spar[w][i];
        const float4* src = (const float4*)(d_Hnew + (b * KQ + p) * HQ);
        float4* dst = (float4*)(d_Hid + (b * KQ + i) * HQ);
        dst[lane]      = src[lane];
        dst[lane + 32] = src[lane + 32];
    }
    // path: carry hidden forward, accumulate path score (emissions[0] quirk)
    {
        const float4* src = (const float4*)(d_Hnew + (NRQ + b) * HQ);
        float4* dst = (float4*)(d_Hid + (NRQ + b) * HQ);
        dst[lane]      = src[lane];
        dst[lane + 32] = src[lane + 32];
        if (lane == 0) {
            int cur = tags[step * BQ + b];
            float trv = d_Cand[(NRQ + b) * TQ + cur];
            d_PS[b] += (trv + emis[b * TQ + cur]) * mask[step * BQ + b];
        }
    }
}

// ---------------- finalize: sum_b (path_score - logsumexp(scores)) ----------------
__global__ void k_final(float* __restrict__ out) {
    __shared__ float red[BQ];
    int b = threadIdx.x;
    float m = -INFINITY;
    for (int i = 0; i < KQ; i++) m = fmaxf(m, d_Sc[b * KQ + i]);
    float s = 0.f;
    for (int i = 0; i < KQ; i++) s += expf(d_Sc[b * KQ + i] - m);
    float lse = m + logf(s);
    red[b] = d_PS[b] - lse;
    __syncthreads();
    for (int off = 128; off; off >>= 1) {
        if (b < off) red[b] += red[b + off];
        __syncthreads();
    }
    if (b == 0) out[0] = red[0];
}

// ---------------- launch ----------------
extern "C" void kernel_launch(void* const* d_in, const int* in_sizes, int n_in,
                              void* d_out, int out_size) {
    const float* emissions = (const float*)d_in[0];
    const int*   tags      = (const int*)  d_in[1];
    const float* mask      = (const float*)d_in[2];
    const float* embedding = (const float*)d_in[3];
    const float* W_ih      = (const float*)d_in[4];
    const float* W_hh      = (const float*)d_in[5];
    const float* b_ih      = (const float*)d_in[6];
    const float* b_hh      = (const float*)d_in[7];
    const float* W_lin     = (const float*)d_in[8];
    const float* b_lin     = (const float*)d_in[9];
    float* out = (float*)d_out;

    k_prep_xg<<<(33 * GQ * 32 + 255) / 256, 256>>>(W_ih, embedding, b_ih);
    k_prep_tr<<<(GQ * HQ + TQ * HQ + 255) / 256, 256>>>(W_hh, W_lin);
    k_prep_h1<<<1, 256>>>(b_hh, W_lin, b_lin);
    k_prep_init<<<BQ / 8, 256>>>(emissions, tags, mask);

    for (int t = 1; t < LQ; t++) {
        k_gru_step<<<NTOTQ / 32, 256>>>(t, emissions, tags, mask, b_hh, b_lin);
        k_select<<<BQ / 8, 256>>>(t, emissions, tags, mask);
    }
    k_final<<<1, 256>>>(out);
}

// round 4
// speedup vs baseline: 1.2517x; 1.2517x over previous
#include <cuda_runtime.h>
#include <math.h>

#define LQ 64
#define BQ 256
#define TQ 32
#define EQ 256
#define HQ 256
#define GQ 768      // 3*H
#define KQ 32
#define NRQ 8192    // B*K beam rows
#define NPB 8       // path blocks (32 chains each)
#define GRIDP (BQ + NPB)

typedef unsigned long long u64;

// ---------------- device scratch ----------------
__device__ float d_XG[33 * GQ];      // x-gates per tag (includes b_ih)
__device__ float d_Wt[HQ * GQ];      // W_hh^T: Wt[k*G + c] = W_hh[c*H + k]
__device__ float d_WtL[HQ * TQ];     // W_lin^T
__device__ float d_h1[HQ];
__device__ float d_trans0[TQ];
__device__ float d_Hid[(NRQ + BQ) * HQ];
__device__ float d_Sc[BQ * KQ];
__device__ int   d_Btags[BQ * KQ];
__device__ float d_PS[BQ];

// ---------------- helpers ----------------
__device__ __forceinline__ float fsig(float x)  { return 1.0f / (1.0f + __expf(-x)); }
__device__ __forceinline__ float ftanh(float x) { return 2.0f / (1.0f + __expf(-2.0f * x)) - 1.0f; }

__device__ __forceinline__ u64 pack2(float lo, float hi) {
    u64 r;
    asm("mov.b64 %0, {%1, %2};" : "=l"(r) : "f"(lo), "f"(hi));
    return r;
}
__device__ __forceinline__ void fma2(u64 &d, u64 a, u64 b) {
    asm("fma.rn.f32x2 %0, %1, %2, %0;" : "+l"(d) : "l"(a), "l"(b));
}

// ---------------- prep: XG[33][768] = W_ih @ emb[t] + b_ih ----------------
__global__ void k_prep_xg(const float* __restrict__ W_ih,
                          const float* __restrict__ emb,
                          const float* __restrict__ b_ih) {
    int o = (blockIdx.x * blockDim.x + threadIdx.x) >> 5;
    int lane = threadIdx.x & 31;
    if (o >= 33 * GQ) return;
    int t = o / GQ, c = o % GQ;
    const float* wr = W_ih + c * EQ;
    const float* er = emb + t * EQ;
    float acc = 0.f;
    for (int k = lane; k < EQ; k += 32) acc += wr[k] * er[k];
    #pragma unroll
    for (int off = 16; off; off >>= 1) acc += __shfl_down_sync(0xffffffffu, acc, off);
    if (lane == 0) d_XG[o] = acc + b_ih[c];
}

// ---------------- prep: transposes ----------------
__global__ void k_prep_tr(const float* __restrict__ W_hh,
                          const float* __restrict__ W_lin) {
    int idx = blockIdx.x * blockDim.x + threadIdx.x;
    if (idx < GQ * HQ) {
        int c = idx / HQ, k = idx % HQ;
        d_Wt[k * GQ + c] = W_hh[idx];
    } else {
        int i2 = idx - GQ * HQ;
        if (i2 < TQ * HQ) {
            int t = i2 / HQ, k = i2 % HQ;
            d_WtL[k * TQ + t] = W_lin[i2];
        }
    }
}

// ---------------- prep: h1 = gru(emb[T], 0), trans0 = lin(h1) ----------------
__global__ void k_prep_h1(const float* __restrict__ b_hh,
                          const float* __restrict__ W_lin,
                          const float* __restrict__ b_lin) {
    __shared__ float h1s[HQ];
    int j = threadIdx.x;
    float ir  = d_XG[32 * GQ + j];
    float iz  = d_XG[32 * GQ + HQ + j];
    float in_ = d_XG[32 * GQ + 2 * HQ + j];
    float r = fsig(ir + b_hh[j]);
    float z = fsig(iz + b_hh[HQ + j]);
    float n = ftanh(in_ + r * b_hh[2 * HQ + j]);
    float h = (1.f - z) * n;   // h0 == 0
    h1s[j] = h;
    d_h1[j] = h;
    __syncthreads();
    if (j < TQ) {
        float acc = b_lin[j];
        const float* wr = W_lin + j * HQ;
        for (int k = 0; k < HQ; k++) acc += wr[k] * h1s[k];
        d_trans0[j] = acc;
    }
}

// ---------------- prep: initial scores / beams / hidden / path score ----------------
__global__ void k_prep_init(const float* __restrict__ emis,
                            const int* __restrict__ tags,
                            const float* __restrict__ mask) {
    int w = threadIdx.x >> 5, lane = threadIdx.x & 31;
    int b = blockIdx.x * 8 + w;
    float m0 = mask[b];
    float v = (d_trans0[lane] + emis[b * TQ + lane]) * m0;
    int rank = 0;
    for (int j = 0; j < 32; j++) {
        float vj = __shfl_sync(0xffffffffu, v, j);
        rank += (vj > v) || (vj == v && j < lane);
    }
    d_Sc[b * KQ + rank]    = v;
    d_Btags[b * KQ + rank] = lane;
    if (lane == 0) {
        int t0 = tags[b];
        d_PS[b] = (d_trans0[t0] + emis[b * TQ + t0]) * m0;
    }
    for (int r = 0; r < KQ; r++) {
        float* dst = d_Hid + (b * KQ + r) * HQ;
        for (int c = lane; c < HQ; c += 32) dst[c] = d_h1[c];
    }
    float* dst = d_Hid + (NRQ + b) * HQ;
    for (int c = lane; c < HQ; c += 32) dst[c] = d_h1[c];
}

// ================= persistent fused stepper =================
// Block b < 256: batch b's 32 beams (GEMM + gates + lin + top-32 select + gather)
// Block >= 256:  32 path chains (GEMM + gates + lin + path-score accumulate)
// All 63 steps run inside the kernel; H lives in smem throughout.
#define SM_H2    0
#define SM_RH    32768
#define SM_ZB    65536
#define SM_CAND  98304
#define SM_STAG  102400
#define SM_SSC   102528
#define SM_SPAR  102656
#define SM_SPS   102784
#define SM_TOTAL 102912

__global__ void __launch_bounds__(256, 2)
k_persist(const float* __restrict__ emis,
          const int* __restrict__ tags,
          const float* __restrict__ mask,
          const float* __restrict__ b_hh,
          const float* __restrict__ b_lin) {
    extern __shared__ char sm[];
    float2* H2   = (float2*)(sm + SM_H2);     // [16][256] flat: row-pairs of H
    float*  RH   = (float*) (sm + SM_RH);     // r-gate, then h' [32][256]
    float*  ZB   = (float*) (sm + SM_ZB);     // z-gate [32][256]
    float*  cand = (float*) (sm + SM_CAND);   // [32][32]
    int*    stag = (int*)   (sm + SM_STAG);   // beam tag per slot / path x-tag
    float*  sSc  = (float*) (sm + SM_SSC);    // scores per slot
    int*    sPar = (int*)   (sm + SM_SPAR);   // parents
    float*  sPS  = (float*) (sm + SM_SPS);    // path scores

    int tid = threadIdx.x;
    int bid = blockIdx.x;
    bool isPath = (bid >= BQ);
    int bo = isPath ? (bid - BQ) * 32 : 0;

    // ---- load initial state ----
    if (!isPath) {
        if (tid < 32) { stag[tid] = d_Btags[bid * KQ + tid]; sSc[tid] = d_Sc[bid * KQ + tid]; }
        const float* src = d_Hid + (bid * KQ) * HQ;
        #pragma unroll
        for (int i = 0; i < 32; i++)
            ((float*)&H2[(i >> 1) * HQ + tid])[i & 1] = src[i * HQ + tid];
    } else {
        if (tid < 32) sPS[tid] = d_PS[bo + tid];
        const float* src = d_Hid + (NRQ + bo) * HQ;
        #pragma unroll
        for (int i = 0; i < 32; i++)
            ((float*)&H2[(i >> 1) * HQ + tid])[i & 1] = src[i * HQ + tid];
    }
    float bh0 = b_hh[tid], bh1 = b_hh[HQ + tid], bh2 = b_hh[2 * HQ + tid];
    float blin = b_lin[tid & 31];
    __syncthreads();

    for (int t = 1; t < LQ; t++) {
        // path blocks: stage this step's input tags into stag
        if (isPath && tid < 32) stag[tid] = tags[(t - 1) * BQ + bo + tid];
        __syncthreads();

        // ---- pass 1: gate columns r (tid) and z (tid+256) ----
        u64 aR[16], aZ[16];
        #pragma unroll
        for (int p = 0; p < 16; p++) { aR[p] = 0ull; aZ[p] = 0ull; }
        {
            const float* Wp = d_Wt + tid;
            #pragma unroll 4
            for (int k = 0; k < HQ; k++) {
                float w0 = Wp[k * GQ];
                float w1 = Wp[k * GQ + HQ];
                u64 W0 = pack2(w0, w0), W1 = pack2(w1, w1);
                #pragma unroll
                for (int p = 0; p < 16; p++) {
                    u64 h = *reinterpret_cast<const u64*>(&H2[p * HQ + k]);
                    fma2(aR[p], h, W0);
                    fma2(aZ[p], h, W1);
                }
            }
        }
        #pragma unroll
        for (int p = 0; p < 16; p++) {
            float2 gr = *(float2*)&aR[p];
            float2 gz = *(float2*)&aZ[p];
            #pragma unroll
            for (int s = 0; s < 2; s++) {
                int r = 2 * p + s;
                int xt = stag[r];
                const float* gi = d_XG + xt * GQ;
                float g0 = s ? gr.y : gr.x;
                float g1 = s ? gz.y : gz.x;
                RH[r * HQ + tid] = fsig(gi[tid] + g0 + bh0);
                ZB[r * HQ + tid] = fsig(gi[HQ + tid] + g1 + bh1);
            }
        }
        // ---- pass 2: gate column n (tid+512); combine to h' ----
        u64 aN[16];
        #pragma unroll
        for (int p = 0; p < 16; p++) aN[p] = 0ull;
        {
            const float* Wp = d_Wt + 2 * HQ + tid;
            #pragma unroll 4
            for (int k = 0; k < HQ; k++) {
                float w2 = Wp[k * GQ];
                u64 W2 = pack2(w2, w2);
                #pragma unroll
                for (int p = 0; p < 16; p++) {
                    u64 h = *reinterpret_cast<const u64*>(&H2[p * HQ + k]);
                    fma2(aN[p], h, W2);
                }
            }
        }
        #pragma unroll
        for (int p = 0; p < 16; p++) {
            float2 gn = *(float2*)&aN[p];
            float2 hpair = H2[p * HQ + tid];
            #pragma unroll
            for (int s = 0; s < 2; s++) {
                int r = 2 * p + s;
                int xt = stag[r];
                const float* gi = d_XG + xt * GQ;
                float g2 = s ? gn.y : gn.x;
                float rr = RH[r * HQ + tid];           // same-thread element
                float nn = ftanh(gi[2 * HQ + tid] + rr * (g2 + bh2));
                float ho = s ? hpair.y : hpair.x;
                float zz = ZB[r * HQ + tid];
                RH[r * HQ + tid] = nn + zz * (ho - nn);  // h'
            }
        }
        __syncthreads();

        // ---- TR = h' @ W_lin^T + b_lin; warp w -> rows 4w..4w+3, lane = tag ----
        int w = tid >> 5, lane = tid & 31;
        float ta0 = blin, ta1 = blin, ta2 = blin, ta3 = blin;
        {
            const float* hr = RH + (4 * w) * HQ;
            const float* wl = d_WtL + lane;
            #pragma unroll 4
            for (int k = 0; k < HQ; k++) {
                float v = wl[k * TQ];
                ta0 += hr[k] * v;
                ta1 += hr[HQ + k] * v;
                ta2 += hr[2 * HQ + k] * v;
                ta3 += hr[3 * HQ + k] * v;
            }
        }
        if (!isPath) {
            float em = emis[(t * BQ + bid) * TQ + lane];
            float m  = mask[t * BQ + bid];
            float ta[4] = {ta0, ta1, ta2, ta3};
            #pragma unroll
            for (int q = 0; q < 4; q++) {
                int r = 4 * w + q;
                float base = sSc[stag[r]];   // quirk: gather prior scores by beam TAG id
                cand[r * TQ + lane] = base + (ta[q] + em) * m;
            }
        } else {
            float ta[4] = {ta0, ta1, ta2, ta3};
            #pragma unroll
            for (int q = 0; q < 4; q++) {
                int r = 4 * w + q;
                int b = bo + r;
                int cur = tags[t * BQ + b];
                if (lane == cur)   // em0 quirk: emissions[0] at every step
                    sPS[r] += (ta[q] + emis[b * TQ + cur]) * mask[t * BQ + b];
            }
        }
        __syncthreads();

        // ---- top-32 select (warp 0, register-resident candidates) ----
        if (!isPath) {
            if (tid < 32) {
                float c[32];
                #pragma unroll
                for (int j = 0; j < 32; j++) c[j] = cand[j * TQ + tid];
                for (int i = 0; i < KQ; i++) {
                    float bv = -INFINITY; int bj = 0;
                    #pragma unroll
                    for (int j = 0; j < 32; j++)
                        if (c[j] > bv) { bv = c[j]; bj = j; }   // '>' keeps smallest flat idx
                    int bi = bj * 32 + tid;
                    #pragma unroll
                    for (int off = 16; off; off >>= 1) {
                        float ov = __shfl_down_sync(0xffffffffu, bv, off);
                        int   oi = __shfl_down_sync(0xffffffffu, bi, off);
                        if (ov > bv || (ov == bv && oi < bi)) { bv = ov; bi = oi; }
                    }
                    bv = __shfl_sync(0xffffffffu, bv, 0);
                    bi = __shfl_sync(0xffffffffu, bi, 0);
                    if (tid == 0) { sSc[i] = bv; stag[i] = bi & 31; sPar[i] = bi >> 5; }
                    if ((bi & 31) == tid) c[bi >> 5] = -INFINITY;
                }
            }
            __syncthreads();
            // gather: new H = h'[parent]
            #pragma unroll
            for (int i = 0; i < 32; i++) {
                float v = RH[sPar[i] * HQ + tid];
                ((float*)&H2[(i >> 1) * HQ + tid])[i & 1] = v;
            }
        } else {
            #pragma unroll
            for (int i = 0; i < 32; i++)
                ((float*)&H2[(i >> 1) * HQ + tid])[i & 1] = RH[i * HQ + tid];
        }
        __syncthreads();
    }

    // ---- writeback final state ----
    if (!isPath) { if (tid < 32) d_Sc[bid * KQ + tid] = sSc[tid]; }
    else if (tid < 32) d_PS[bo + tid] = sPS[tid];
}

// ---------------- finalize ----------------
__global__ void k_final(float* __restrict__ out) {
    __shared__ float red[BQ];
    int b = threadIdx.x;
    float m = -INFINITY;
    for (int i = 0; i < KQ; i++) m = fmaxf(m, d_Sc[b * KQ + i]);
    float s = 0.f;
    for (int i = 0; i < KQ; i++) s += expf(d_Sc[b * KQ + i] - m);
    float lse = m + logf(s);
    red[b] = d_PS[b] - lse;
    __syncthreads();
    for (int off = 128; off; off >>= 1) {
        if (b < off) red[b] += red[b + off];
        __syncthreads();
    }
    if (b == 0) out[0] = red[0];
}

// ---------------- launch ----------------
extern "C" void kernel_launch(void* const* d_in, const int* in_sizes, int n_in,
                              void* d_out, int out_size) {
    const float* emissions = (const float*)d_in[0];
    const int*   tags      = (const int*)  d_in[1];
    const float* mask      = (const float*)d_in[2];
    const float* embedding = (const float*)d_in[3];
    const float* W_ih      = (const float*)d_in[4];
    const float* W_hh      = (const float*)d_in[5];
    const float* b_ih      = (const float*)d_in[6];
    const float* b_hh      = (const float*)d_in[7];
    const float* W_lin     = (const float*)d_in[8];
    const float* b_lin     = (const float*)d_in[9];
    float* out = (float*)d_out;

    cudaFuncSetAttribute(k_persist, cudaFuncAttributeMaxDynamicSharedMemorySize, SM_TOTAL);

    k_prep_xg<<<(33 * GQ * 32 + 255) / 256, 256>>>(W_ih, embedding, b_ih);
    k_prep_tr<<<(GQ * HQ + TQ * HQ + 255) / 256, 256>>>(W_hh, W_lin);
    k_prep_h1<<<1, 256>>>(b_hh, W_lin, b_lin);
    k_prep_init<<<BQ / 8, 256>>>(emissions, tags, mask);

    k_persist<<<GRIDP, 256, SM_TOTAL>>>(emissions, tags, mask, b_hh, b_lin);

    k_final<<<1, 256>>>(out);
}